// round 16
// baseline (speedup 1.0000x reference)
#include <cuda_runtime.h>
#include <cuda_bf16.h>
#include <cstdint>

// ---------------- problem constants ----------------
#define S_ROWS 16384
#define K_DIM  1024
#define D_TOT  6400
#define BINS   20

// ---------------- tiling ----------------
#define BM 256
#define BN 128
#define BK 64
#define KT (K_DIM / BK)          // 16
#define NTHREADS 512             // 16 warps: 4(M) x 4(N), warp tile 64x32

#define PLANE_A 32768            // 256 rows x 128B
#define PLANE_B_SZ 16384         // 128 rows x 128B
#define OFF_BH (2 * PLANE_A)                 // 65536
#define OFF_BL (OFF_BH + PLANE_B_SZ)         // 81920
#define STAGE_B (OFF_BL + PLANE_B_SZ)        // 98304 (96KB)
#define OFF_META (2 * STAGE_B)               // 196608
#define OFF_MBAR (OFF_META + 3 * BN * 4)     // 198144 (full[2], empty[2])
#define SMEM_TOTAL (OFF_MBAR + 4 * 8)        // 198176

// ---------------- global scratch ----------------
__device__ __nv_bfloat16 g_xhi[S_ROWS * K_DIM];
__device__ __nv_bfloat16 g_xlo[S_ROWS * K_DIM];
__device__ __nv_bfloat16 g_whi[D_TOT * K_DIM];
__device__ __nv_bfloat16 g_wlo[D_TOT * K_DIM];
__device__ float g_hist[D_TOT * BINS];

// ---------------- helpers ----------------
__device__ __forceinline__ uint32_t smem_u32(const void* p) {
    uint32_t a;
    asm("{ .reg .u64 t; cvta.to.shared.u64 t, %1; cvt.u32.u64 %0, t; }"
        : "=r"(a) : "l"(p));
    return a;
}
__device__ __forceinline__ uint32_t sw128(uint32_t off) {
    return off ^ ((off >> 3) & 0x70);
}
__device__ __forceinline__ void cp16(uint32_t s, const void* g) {
    asm volatile("cp.async.cg.shared.global [%0], [%1], 16;" :: "r"(s), "l"(g));
}
__device__ __forceinline__ void mbar_init(uint32_t a, uint32_t cnt) {
    asm volatile("mbarrier.init.shared.b64 [%0], %1;" :: "r"(a), "r"(cnt) : "memory");
}
__device__ __forceinline__ void mbar_arrive(uint32_t a) {
    asm volatile("mbarrier.arrive.shared.b64 _, [%0];" :: "r"(a) : "memory");
}
// .noinc: consume one preprogrammed arrival on cp.async completion (cuda::pipeline pattern)
__device__ __forceinline__ void cp_arrive(uint32_t a) {
    asm volatile("cp.async.mbarrier.arrive.noinc.shared.b64 [%0];" :: "r"(a) : "memory");
}
__device__ __forceinline__ void mbar_wait(uint32_t a, uint32_t parity) {
    asm volatile(
        "{\n\t.reg .pred P;\n\t"
        "WL_%=:\n\t"
        "mbarrier.try_wait.parity.shared.b64 P, [%0], %1, 0x989680;\n\t"
        "@P bra WD_%=;\n\t"
        "bra WL_%=;\n\t"
        "WD_%=:\n\t}"
        :: "r"(a), "r"(parity) : "memory");
}
__device__ __forceinline__ void ldsm4(uint32_t* r, uint32_t addr) {
    asm volatile("ldmatrix.sync.aligned.m8n8.x4.shared.b16 {%0,%1,%2,%3}, [%4];"
        : "=r"(r[0]), "=r"(r[1]), "=r"(r[2]), "=r"(r[3]) : "r"(addr));
}
__device__ __forceinline__ void mma_bf16(float* d, const uint32_t* a,
                                         uint32_t b0, uint32_t b1) {
    asm volatile(
        "mma.sync.aligned.m16n8k16.row.col.f32.bf16.bf16.f32 "
        "{%0,%1,%2,%3}, {%4,%5,%6,%7}, {%8,%9}, {%0,%1,%2,%3};"
        : "+f"(d[0]), "+f"(d[1]), "+f"(d[2]), "+f"(d[3])
        : "r"(a[0]), "r"(a[1]), "r"(a[2]), "r"(a[3]), "r"(b0), "r"(b1));
}

// ---------------- pre-split: fp32 -> bf16 hi/lo planes ----------------
__global__ void split_kernel(const float4* __restrict__ src,
                             uint2* __restrict__ hi, uint2* __restrict__ lo, int n4)
{
    int i = blockIdx.x * blockDim.x + threadIdx.x;
    if (i >= n4) return;
    float4 v = src[i];
    uint32_t h0, h1, g0, g1;
    asm("cvt.rn.bf16x2.f32 %0, %1, %2;" : "=r"(h0) : "f"(v.y), "f"(v.x));
    asm("cvt.rn.bf16x2.f32 %0, %1, %2;" : "=r"(h1) : "f"(v.w), "f"(v.z));
    float l0 = v.x - __uint_as_float(h0 << 16);
    float l1 = v.y - __uint_as_float(h0 & 0xFFFF0000u);
    float l2 = v.z - __uint_as_float(h1 << 16);
    float l3 = v.w - __uint_as_float(h1 & 0xFFFF0000u);
    asm("cvt.rn.bf16x2.f32 %0, %1, %2;" : "=r"(g0) : "f"(l1), "f"(l0));
    asm("cvt.rn.bf16x2.f32 %0, %1, %2;" : "=r"(g1) : "f"(l3), "f"(l2));
    hi[i] = make_uint2(h0, h1);
    lo[i] = make_uint2(g0, g1);
}

__global__ void zero_hist_kernel() {
    int i = blockIdx.x * blockDim.x + threadIdx.x;
    if (i < D_TOT * BINS) g_hist[i] = 0.0f;
}

// ---------------- fused GEMM + histogram ----------------
__global__ __launch_bounds__(NTHREADS, 1)
void gemm_hist_kernel(const float* __restrict__ mins, const float* __restrict__ maxs)
{
    extern __shared__ char smem[];
    const uint32_t sb = smem_u32(smem);
    const int tid  = threadIdx.x;
    const int wid  = tid >> 5;
    const int lane = tid & 31;
    const int wm = wid & 3;          // warp M index (0..3) -> rows wm*64
    const int wn = wid >> 2;         // warp N index (0..3) -> cols wn*32

    const int m0  = blockIdx.y * BM;
    const int n0t = blockIdx.x * BN;

    const __nv_bfloat16* Ah = g_xhi + (size_t)m0 * K_DIM;
    const __nv_bfloat16* Al = g_xlo + (size_t)m0 * K_DIM;
    const __nv_bfloat16* Bh = g_whi + (size_t)n0t * K_DIM;
    const __nv_bfloat16* Bl = g_wlo + (size_t)n0t * K_DIM;

    float* mnS = (float*)(smem + OFF_META);
    float* mxS = mnS + BN;
    float* scS = mxS + BN;
    if (tid < BN) {
        float mn = mins[n0t + tid], mx = maxs[n0t + tid];
        mnS[tid] = mn; mxS[tid] = mx;
        scS[tid] = (float)BINS / (mx - mn);
    }

    // mbarriers: full[s] (512 cp-completion arrivals, .noinc), empty[s] (16 warp arrivals)
    const uint32_t mb_full0  = sb + OFF_MBAR;
    const uint32_t mb_full1  = sb + OFF_MBAR + 8;
    const uint32_t mb_empty0 = sb + OFF_MBAR + 16;
    const uint32_t mb_empty1 = sb + OFF_MBAR + 24;
    if (tid == 0) {
        mbar_init(mb_full0, NTHREADS);
        mbar_init(mb_full1, NTHREADS);
        mbar_init(mb_empty0, 16);
        mbar_init(mb_empty1, 16);
    }
    __syncthreads();

    // loader: 512 threads; 128B rows as 8 x 16B chunks
    const int lrow = tid >> 3;       // 0..63
    const int lcol = tid & 7;

    auto load_stage = [&](int kt) {
        const uint32_t st = sb + (uint32_t)((kt & 1) * STAGE_B);
        const size_t kb = (size_t)kt * BK + lcol * 8;
        #pragma unroll
        for (int i = 0; i < 4; ++i) {            // A: 256 rows
            int row = lrow + 64 * i;
            uint32_t soff = sw128((uint32_t)(row * 128 + lcol * 16));
            size_t go = (size_t)row * K_DIM + kb;
            cp16(st + soff, Ah + go);
            cp16(st + PLANE_A + soff, Al + go);
        }
        #pragma unroll
        for (int i = 0; i < 2; ++i) {            // B: 128 rows
            int row = lrow + 64 * i;
            uint32_t soff = sw128((uint32_t)(row * 128 + lcol * 16));
            size_t go = (size_t)row * K_DIM + kb;
            cp16(st + OFF_BH + soff, Bh + go);
            cp16(st + OFF_BL + soff, Bl + go);
        }
    };

    float acc[4][4][4];
    #pragma unroll
    for (int i = 0; i < 4; ++i)
        #pragma unroll
        for (int j = 0; j < 4; ++j)
            #pragma unroll
            for (int r = 0; r < 4; ++r) acc[i][j][r] = 0.0f;

    // prologue: fill both stages
    load_stage(0); cp_arrive(mb_full0);
    load_stage(1); cp_arrive(mb_full1);

    const int l15   = lane & 15;
    const int khalf = (lane >> 4) << 4;   // k-half byte offset (0 or 16)

    int fp0 = 0, fp1 = 0, ep0 = 0, ep1 = 0;   // parities

    for (int kt = 0; kt < KT; ++kt) {
        const int s = kt & 1;
        const uint32_t mbf = s ? mb_full1 : mb_full0;
        const uint32_t mbe = s ? mb_empty1 : mb_empty0;

        // wait for stage data
        if (s) { mbar_wait(mbf, fp1); fp1 ^= 1; }
        else   { mbar_wait(mbf, fp0); fp0 ^= 1; }

        const uint32_t st = sb + (uint32_t)(s * STAGE_B);
        #pragma unroll
        for (int ks = 0; ks < BK / 16; ++ks) {
            uint32_t bfr[2][2][4];
            #pragma unroll
            for (int p = 0; p < 2; ++p)
                #pragma unroll
                for (int ng = 0; ng < 2; ++ng) {
                    int nrow = wn * 32 + ng * 16 + l15;
                    uint32_t off = (uint32_t)(nrow * 128 + ks * 32) + khalf;
                    ldsm4(bfr[p][ng], st + OFF_BH + p * PLANE_B_SZ + sw128(off));
                }
            #pragma unroll
            for (int mf = 0; mf < 4; ++mf) {
                uint32_t af[2][4];
                int arow = wm * 64 + mf * 16 + l15;
                uint32_t off = (uint32_t)(arow * 128 + ks * 32) + khalf;
                ldsm4(af[0], st + sw128(off));
                ldsm4(af[1], st + PLANE_A + sw128(off));
                #pragma unroll
                for (int nf = 0; nf < 4; ++nf) {
                    int ng = nf >> 1, h = nf & 1;
                    mma_bf16(acc[mf][nf], af[0], bfr[0][ng][h], bfr[0][ng][2 + h]);
                    mma_bf16(acc[mf][nf], af[0], bfr[1][ng][h], bfr[1][ng][2 + h]);
                    mma_bf16(acc[mf][nf], af[1], bfr[0][ng][h], bfr[0][ng][2 + h]);
                }
            }
        }

        // this warp is done with stage s
        if (lane == 0) mbar_arrive(mbe);

        // refill stage s for k-tile kt+2 once all warps drained it
        if (kt + 2 < KT) {
            if (s) { mbar_wait(mbe, ep1); ep1 ^= 1; }
            else   { mbar_wait(mbe, ep0); ep0 ^= 1; }
            load_stage(kt + 2);
            cp_arrive(mbf);
        }
    }
    __syncthreads();

    // ---------------- histogram epilogue ----------------
    // 16 warp-private hists of 32 cols x 20 bins = 40KB (reuse stage smem)
    float* hall = (float*)smem;
    for (int i = tid; i < 16 * 32 * BINS; i += NTHREADS) hall[i] = 0.0f;
    __syncthreads();

    float* hw = hall + wid * (32 * BINS);
    const int q = lane & 3;
    #pragma unroll
    for (int nf = 0; nf < 4; ++nf) {
        #pragma unroll
        for (int half = 0; half < 2; ++half) {
            int lc = nf * 8 + 2 * q + half;      // col within warp's 32
            int c  = wn * 32 + lc;
            float mn = mnS[c], mx = mxS[c], sc = scS[c];
            #pragma unroll
            for (int mf = 0; mf < 4; ++mf)
                #pragma unroll
                for (int rp = 0; rp < 2; ++rp) {
                    float p = acc[mf][nf][2 * rp + half];
                    if (p >= mn && p <= mx) {
                        int b = min((int)((p - mn) * sc), BINS - 1);
                        atomicAdd(&hw[lc * BINS + b], 1.0f);
                    }
                }
        }
    }
    __syncthreads();

    // merge the 4 warp copies per column group -> global atomics
    for (int i = tid; i < BN * BINS; i += NTHREADS) {
        int c = i / BINS, b = i - c * BINS;
        int cwn = c >> 5, lc = c & 31;
        float s = 0.0f;
        #pragma unroll
        for (int k = 0; k < 4; ++k)
            s += hall[(cwn * 4 + k) * (32 * BINS) + lc * BINS + b];
        if (s != 0.0f)
            atomicAdd(&g_hist[(size_t)n0t * BINS + i], s);
    }
}

// ---------------- normalize ----------------
__global__ void normalize_kernel(float* __restrict__ out)
{
    int row  = blockIdx.x * 4 + (threadIdx.x >> 5);
    int lane = threadIdx.x & 31;
    if (row >= D_TOT) return;
    float v = (lane < BINS) ? g_hist[row * BINS + lane] : 0.0f;
    float s = v * v;
    #pragma unroll
    for (int o = 16; o; o >>= 1) s += __shfl_xor_sync(0xFFFFFFFFu, s, o);
    float denom = fmaxf(sqrtf(s), 1e-12f);
    if (lane < BINS) out[row * BINS + lane] = v / denom;
}

extern "C" void kernel_launch(void* const* d_in, const int* in_sizes, int n_in,
                              void* d_out, int out_size)
{
    const float* x    = (const float*)d_in[0];
    const float* W    = (const float*)d_in[1];
    const float* mins = (const float*)d_in[2];
    const float* maxs = (const float*)d_in[3];
    float* out = (float*)d_out;

    static int attr_set = 0;
    if (!attr_set) {
        cudaFuncSetAttribute(gemm_hist_kernel,
                             cudaFuncAttributeMaxDynamicSharedMemorySize, SMEM_TOTAL);
        attr_set = 1;
    }

    __nv_bfloat16 *xhi, *xlo, *whi, *wlo;
    cudaGetSymbolAddress((void**)&xhi, g_xhi);
    cudaGetSymbolAddress((void**)&xlo, g_xlo);
    cudaGetSymbolAddress((void**)&whi, g_whi);
    cudaGetSymbolAddress((void**)&wlo, g_wlo);

    int nx4 = S_ROWS * K_DIM / 4;
    int nw4 = D_TOT * K_DIM / 4;
    split_kernel<<<(nx4 + 255) / 256, 256>>>((const float4*)x, (uint2*)xhi, (uint2*)xlo, nx4);
    split_kernel<<<(nw4 + 255) / 256, 256>>>((const float4*)W, (uint2*)whi, (uint2*)wlo, nw4);
    zero_hist_kernel<<<(D_TOT * BINS + 255) / 256, 256>>>();

    dim3 grid(D_TOT / BN, S_ROWS / BM);   // (50, 64)
    gemm_hist_kernel<<<grid, NTHREADS, SMEM_TOTAL>>>(mins, maxs);

    normalize_kernel<<<(D_TOT + 3) / 4, 128>>>(out);
}

// round 17
// speedup vs baseline: 1.0120x; 1.0120x over previous
#include <cuda_runtime.h>
#include <cuda_bf16.h>
#include <cstdint>

// ---------------- problem constants ----------------
#define S_ROWS 16384
#define K_DIM  1024
#define D_TOT  6400
#define BINS   20

// ---------------- tiling ----------------
#define BM 256
#define BN 128
#define BK 64
#define KT (K_DIM / BK)          // 16
#define NTHREADS 512             // 16 warps: 4(M) x 4(N), warp tile 64x32

#define PLANE_A 32768            // 256 rows x 128B
#define PLANE_B_SZ 16384         // 128 rows x 128B
#define OFF_BH (2 * PLANE_A)                 // 65536
#define OFF_BL (OFF_BH + PLANE_B_SZ)         // 81920
#define STAGE_B (OFF_BL + PLANE_B_SZ)        // 98304 (96KB)
#define OFF_META (2 * STAGE_B)               // 196608
#define OFF_MBAR (OFF_META + 3 * BN * 4)     // 198144 (full[2], empty[2])
#define SMEM_TOTAL (OFF_MBAR + 4 * 8)        // 198176

// ---------------- global scratch ----------------
__device__ __nv_bfloat16 g_xhi[S_ROWS * K_DIM];
__device__ __nv_bfloat16 g_xlo[S_ROWS * K_DIM];
__device__ __nv_bfloat16 g_whi[D_TOT * K_DIM];
__device__ __nv_bfloat16 g_wlo[D_TOT * K_DIM];
__device__ float g_hist[D_TOT * BINS];

// ---------------- helpers ----------------
__device__ __forceinline__ uint32_t smem_u32(const void* p) {
    uint32_t a;
    asm("{ .reg .u64 t; cvta.to.shared.u64 t, %1; cvt.u32.u64 %0, t; }"
        : "=r"(a) : "l"(p));
    return a;
}
__device__ __forceinline__ uint32_t sw128(uint32_t off) {
    return off ^ ((off >> 3) & 0x70);
}
__device__ __forceinline__ void cp16(uint32_t s, const void* g) {
    asm volatile("cp.async.cg.shared.global [%0], [%1], 16;" :: "r"(s), "l"(g));
}
__device__ __forceinline__ void mbar_init(uint32_t a, uint32_t cnt) {
    asm volatile("mbarrier.init.shared.b64 [%0], %1;" :: "r"(a), "r"(cnt) : "memory");
}
__device__ __forceinline__ void mbar_arrive(uint32_t a) {
    asm volatile("mbarrier.arrive.shared.b64 _, [%0];" :: "r"(a) : "memory");
}
// .noinc: consume one preprogrammed arrival on cp.async completion
__device__ __forceinline__ void cp_arrive(uint32_t a) {
    asm volatile("cp.async.mbarrier.arrive.noinc.shared.b64 [%0];" :: "r"(a) : "memory");
}
__device__ __forceinline__ void mbar_wait(uint32_t a, uint32_t parity) {
    asm volatile(
        "{\n\t.reg .pred P;\n\t"
        "WL_%=:\n\t"
        "mbarrier.try_wait.parity.shared.b64 P, [%0], %1, 0x989680;\n\t"
        "@P bra WD_%=;\n\t"
        "bra WL_%=;\n\t"
        "WD_%=:\n\t}"
        :: "r"(a), "r"(parity) : "memory");
}
__device__ __forceinline__ void ldsm4(uint32_t* r, uint32_t addr) {
    asm volatile("ldmatrix.sync.aligned.m8n8.x4.shared.b16 {%0,%1,%2,%3}, [%4];"
        : "=r"(r[0]), "=r"(r[1]), "=r"(r[2]), "=r"(r[3]) : "r"(addr));
}
__device__ __forceinline__ void mma_bf16(float* d, const uint32_t* a,
                                         uint32_t b0, uint32_t b1) {
    asm volatile(
        "mma.sync.aligned.m16n8k16.row.col.f32.bf16.bf16.f32 "
        "{%0,%1,%2,%3}, {%4,%5,%6,%7}, {%8,%9}, {%0,%1,%2,%3};"
        : "+f"(d[0]), "+f"(d[1]), "+f"(d[2]), "+f"(d[3])
        : "r"(a[0]), "r"(a[1]), "r"(a[2]), "r"(a[3]), "r"(b0), "r"(b1));
}

// ---------------- pre-split: fp32 -> bf16 hi/lo planes ----------------
__global__ void split_kernel(const float4* __restrict__ src,
                             uint2* __restrict__ hi, uint2* __restrict__ lo, int n4)
{
    int i = blockIdx.x * blockDim.x + threadIdx.x;
    if (i >= n4) return;
    float4 v = src[i];
    uint32_t h0, h1, g0, g1;
    asm("cvt.rn.bf16x2.f32 %0, %1, %2;" : "=r"(h0) : "f"(v.y), "f"(v.x));
    asm("cvt.rn.bf16x2.f32 %0, %1, %2;" : "=r"(h1) : "f"(v.w), "f"(v.z));
    float l0 = v.x - __uint_as_float(h0 << 16);
    float l1 = v.y - __uint_as_float(h0 & 0xFFFF0000u);
    float l2 = v.z - __uint_as_float(h1 << 16);
    float l3 = v.w - __uint_as_float(h1 & 0xFFFF0000u);
    asm("cvt.rn.bf16x2.f32 %0, %1, %2;" : "=r"(g0) : "f"(l1), "f"(l0));
    asm("cvt.rn.bf16x2.f32 %0, %1, %2;" : "=r"(g1) : "f"(l3), "f"(l2));
    hi[i] = make_uint2(h0, h1);
    lo[i] = make_uint2(g0, g1);
}

__global__ void zero_hist_kernel() {
    int i = blockIdx.x * blockDim.x + threadIdx.x;
    if (i < D_TOT * BINS) g_hist[i] = 0.0f;
}

// ---------------- fused GEMM + histogram ----------------
__global__ __launch_bounds__(NTHREADS, 1)
void gemm_hist_kernel(const float* __restrict__ mins, const float* __restrict__ maxs)
{
    extern __shared__ char smem[];
    const uint32_t sb = smem_u32(smem);
    const int tid  = threadIdx.x;
    const int wid  = tid >> 5;
    const int lane = tid & 31;
    const int wm = wid & 3;          // warp M index (0..3) -> rows wm*64
    const int wn = wid >> 2;         // warp N index (0..3) -> cols wn*32

    const int m0  = blockIdx.y * BM;
    const int n0t = blockIdx.x * BN;

    const __nv_bfloat16* Ah = g_xhi + (size_t)m0 * K_DIM;
    const __nv_bfloat16* Al = g_xlo + (size_t)m0 * K_DIM;
    const __nv_bfloat16* Bh = g_whi + (size_t)n0t * K_DIM;
    const __nv_bfloat16* Bl = g_wlo + (size_t)n0t * K_DIM;

    float* mnS = (float*)(smem + OFF_META);
    float* mxS = mnS + BN;
    float* scS = mxS + BN;
    if (tid < BN) {
        float mn = mins[n0t + tid], mx = maxs[n0t + tid];
        mnS[tid] = mn; mxS[tid] = mx;
        scS[tid] = (float)BINS / (mx - mn);
    }

    const uint32_t mb_full0  = sb + OFF_MBAR;
    const uint32_t mb_full1  = sb + OFF_MBAR + 8;
    const uint32_t mb_empty0 = sb + OFF_MBAR + 16;
    const uint32_t mb_empty1 = sb + OFF_MBAR + 24;
    if (tid == 0) {
        mbar_init(mb_full0, NTHREADS);
        mbar_init(mb_full1, NTHREADS);
        mbar_init(mb_empty0, 16);
        mbar_init(mb_empty1, 16);
    }
    __syncthreads();

    // loader: 512 threads; 128B rows as 8 x 16B chunks
    const int lrow = tid >> 3;       // 0..63
    const int lcol = tid & 7;

    auto load_stage = [&](int kt) {
        const uint32_t st = sb + (uint32_t)((kt & 1) * STAGE_B);
        const size_t kb = (size_t)kt * BK + lcol * 8;
        #pragma unroll
        for (int i = 0; i < 4; ++i) {            // A: 256 rows
            int row = lrow + 64 * i;
            uint32_t soff = sw128((uint32_t)(row * 128 + lcol * 16));
            size_t go = (size_t)row * K_DIM + kb;
            cp16(st + soff, Ah + go);
            cp16(st + PLANE_A + soff, Al + go);
        }
        #pragma unroll
        for (int i = 0; i < 2; ++i) {            // B: 128 rows
            int row = lrow + 64 * i;
            uint32_t soff = sw128((uint32_t)(row * 128 + lcol * 16));
            size_t go = (size_t)row * K_DIM + kb;
            cp16(st + OFF_BH + soff, Bh + go);
            cp16(st + OFF_BL + soff, Bl + go);
        }
    };

    float acc[4][4][4];
    #pragma unroll
    for (int i = 0; i < 4; ++i)
        #pragma unroll
        for (int j = 0; j < 4; ++j)
            #pragma unroll
            for (int r = 0; r < 4; ++r) acc[i][j][r] = 0.0f;

    // prologue: fill both stages
    load_stage(0); cp_arrive(mb_full0);
    load_stage(1); cp_arrive(mb_full1);

    const int l15   = lane & 15;
    const int khalf = (lane >> 4) << 4;   // k-half byte offset (0 or 16)

    // fragment buffers: A double-buffered (prefetch 1 mf ahead), B single
    uint32_t afr[2][2][4];    // [buf][plane][4]
    uint32_t bfr[2][2][4];    // [plane][ng][4]

    // A fragment load: both planes for (mf, ks) into buffer b
    auto ld_af = [&](uint32_t st, int mf, int ks, int b) {
        int arow = wm * 64 + mf * 16 + l15;
        uint32_t off = (uint32_t)(arow * 128 + ks * 32) + khalf;
        ldsm4(afr[b][0], st + sw128(off));
        ldsm4(afr[b][1], st + PLANE_A + sw128(off));
    };
    // B fragments for ks (both planes, both n-groups)
    auto ld_bfr = [&](uint32_t st, int ks) {
        #pragma unroll
        for (int p = 0; p < 2; ++p)
            #pragma unroll
            for (int ng = 0; ng < 2; ++ng) {
                int nrow = wn * 32 + ng * 16 + l15;
                uint32_t off = (uint32_t)(nrow * 128 + ks * 32) + khalf;
                ldsm4(bfr[p][ng], st + OFF_BH + p * PLANE_B_SZ + sw128(off));
            }
    };

    int fp0 = 0, fp1 = 0, ep0 = 0, ep1 = 0;   // parities

    for (int kt = 0; kt < KT; ++kt) {
        const int s = kt & 1;
        const uint32_t mbf = s ? mb_full1 : mb_full0;
        const uint32_t mbe = s ? mb_empty1 : mb_empty0;

        if (s) { mbar_wait(mbf, fp1); fp1 ^= 1; }
        else   { mbar_wait(mbf, fp0); fp0 ^= 1; }

        const uint32_t st = sb + (uint32_t)(s * STAGE_B);

        // stage head: B(ks0) + A(mf0,ks0)
        ld_bfr(st, 0);
        ld_af(st, 0, 0, 0);

        #pragma unroll
        for (int ks = 0; ks < BK / 16; ++ks) {
            #pragma unroll
            for (int mf = 0; mf < 4; ++mf) {
                const int cb = mf & 1;
                // prefetch next A fragments (covered by the 12 MMAs below)
                if (mf < 3)      ld_af(st, mf + 1, ks, cb ^ 1);
                else if (ks < 3) ld_af(st, 0, ks + 1, 0);
                #pragma unroll
                for (int nf = 0; nf < 4; ++nf) {
                    int ng = nf >> 1, h = nf & 1;
                    mma_bf16(acc[mf][nf], afr[cb][0], bfr[0][ng][h], bfr[0][ng][2 + h]);
                    mma_bf16(acc[mf][nf], afr[cb][0], bfr[1][ng][h], bfr[1][ng][2 + h]);
                    mma_bf16(acc[mf][nf], afr[cb][1], bfr[0][ng][h], bfr[0][ng][2 + h]);
                }
            }
            if (ks < 3) ld_bfr(st, ks + 1);
        }

        // this warp is done with stage s
        if (lane == 0) mbar_arrive(mbe);

        // refill stage s for k-tile kt+2 once all warps drained it
        if (kt + 2 < KT) {
            if (s) { mbar_wait(mbe, ep1); ep1 ^= 1; }
            else   { mbar_wait(mbe, ep0); ep0 ^= 1; }
            load_stage(kt + 2);
            cp_arrive(mbf);
        }
    }
    __syncthreads();

    // ---------------- histogram epilogue ----------------
    float* hall = (float*)smem;      // 16 x 32 x 20 = 40KB (reuse stage smem)
    for (int i = tid; i < 16 * 32 * BINS; i += NTHREADS) hall[i] = 0.0f;
    __syncthreads();

    float* hw = hall + wid * (32 * BINS);
    const int q = lane & 3;
    #pragma unroll
    for (int nf = 0; nf < 4; ++nf) {
        #pragma unroll
        for (int half = 0; half < 2; ++half) {
            int lc = nf * 8 + 2 * q + half;      // col within warp's 32
            int c  = wn * 32 + lc;
            float mn = mnS[c], mx = mxS[c], sc = scS[c];
            #pragma unroll
            for (int mf = 0; mf < 4; ++mf)
                #pragma unroll
                for (int rp = 0; rp < 2; ++rp) {
                    float p = acc[mf][nf][2 * rp + half];
                    if (p >= mn && p <= mx) {
                        int b = min((int)((p - mn) * sc), BINS - 1);
                        atomicAdd(&hw[lc * BINS + b], 1.0f);
                    }
                }
        }
    }
    __syncthreads();

    for (int i = tid; i < BN * BINS; i += NTHREADS) {
        int c = i / BINS, b = i - c * BINS;
        int cwn = c >> 5, lc = c & 31;
        float s = 0.0f;
        #pragma unroll
        for (int k = 0; k < 4; ++k)
            s += hall[(cwn * 4 + k) * (32 * BINS) + lc * BINS + b];
        if (s != 0.0f)
            atomicAdd(&g_hist[(size_t)n0t * BINS + i], s);
    }
}

// ---------------- normalize ----------------
__global__ void normalize_kernel(float* __restrict__ out)
{
    int row  = blockIdx.x * 4 + (threadIdx.x >> 5);
    int lane = threadIdx.x & 31;
    if (row >= D_TOT) return;
    float v = (lane < BINS) ? g_hist[row * BINS + lane] : 0.0f;
    float s = v * v;
    #pragma unroll
    for (int o = 16; o; o >>= 1) s += __shfl_xor_sync(0xFFFFFFFFu, s, o);
    float denom = fmaxf(sqrtf(s), 1e-12f);
    if (lane < BINS) out[row * BINS + lane] = v / denom;
}

extern "C" void kernel_launch(void* const* d_in, const int* in_sizes, int n_in,
                              void* d_out, int out_size)
{
    const float* x    = (const float*)d_in[0];
    const float* W    = (const float*)d_in[1];
    const float* mins = (const float*)d_in[2];
    const float* maxs = (const float*)d_in[3];
    float* out = (float*)d_out;

    static int attr_set = 0;
    if (!attr_set) {
        cudaFuncSetAttribute(gemm_hist_kernel,
                             cudaFuncAttributeMaxDynamicSharedMemorySize, SMEM_TOTAL);
        attr_set = 1;
    }

    __nv_bfloat16 *xhi, *xlo, *whi, *wlo;
    cudaGetSymbolAddress((void**)&xhi, g_xhi);
    cudaGetSymbolAddress((void**)&xlo, g_xlo);
    cudaGetSymbolAddress((void**)&whi, g_whi);
    cudaGetSymbolAddress((void**)&wlo, g_wlo);

    int nx4 = S_ROWS * K_DIM / 4;
    int nw4 = D_TOT * K_DIM / 4;
    split_kernel<<<(nx4 + 255) / 256, 256>>>((const float4*)x, (uint2*)xhi, (uint2*)xlo, nx4);
    split_kernel<<<(nw4 + 255) / 256, 256>>>((const float4*)W, (uint2*)whi, (uint2*)wlo, nw4);
    zero_hist_kernel<<<(D_TOT * BINS + 255) / 256, 256>>>();

    dim3 grid(D_TOT / BN, S_ROWS / BM);   // (50, 64)
    gemm_hist_kernel<<<grid, NTHREADS, SMEM_TOTAL>>>(mins, maxs);

    normalize_kernel<<<(D_TOT + 3) / 4, 128>>>(out);
}